// round 2
// baseline (speedup 1.0000x reference)
#include <cuda_runtime.h>
#include <math.h>

#define TT 2048
#define NH 12

// scratch (device globals: no allocations allowed)
__device__ float g_q[TT * 768];
__device__ float g_k[TT * 768];
__device__ float g_v[TT * 768];
__device__ float g_y[TT * 768];

// ---------------------------------------------------------------------------
// GEMM core: C[M,768] = A[M,768] * B[768,768]^T   (both row-major, K inner)
// BM=128, BN=128, BK=16, 256 threads, 8x8 micro-tile (split column groups)
// ---------------------------------------------------------------------------
__device__ __forceinline__ void gemm_body(
    const float* __restrict__ A, const float* __restrict__ B,
    float* __restrict__ C, const float* __restrict__ vi,
    const float* __restrict__ lamb_p, bool blend,
    float (*As)[132], float (*Bs)[132])
{
    const int tid = threadIdx.x;
    const int bm = blockIdx.y * 128;
    const int bn = blockIdx.x * 128;
    const int ty = tid >> 4;        // 0..15
    const int tx = tid & 15;        // 0..15
    const int lr = tid >> 2;        // 0..63
    const int lc = (tid & 3) << 2;  // 0,4,8,12

    const float* Ap = A + (bm + lr) * 768 + lc;
    const float* Bp = B + (bn + lr) * 768 + lc;

    float acc[8][8];
#pragma unroll
    for (int i = 0; i < 8; i++)
#pragma unroll
        for (int j = 0; j < 8; j++) acc[i][j] = 0.f;

    float4 a0 = *(const float4*)(Ap);
    float4 a1 = *(const float4*)(Ap + 64 * 768);
    float4 b0 = *(const float4*)(Bp);
    float4 b1 = *(const float4*)(Bp + 64 * 768);

    for (int k0 = 16; k0 <= 768; k0 += 16) {
        // store current tile (transposed) to smem
        As[lc + 0][lr] = a0.x; As[lc + 1][lr] = a0.y; As[lc + 2][lr] = a0.z; As[lc + 3][lr] = a0.w;
        As[lc + 0][lr + 64] = a1.x; As[lc + 1][lr + 64] = a1.y; As[lc + 2][lr + 64] = a1.z; As[lc + 3][lr + 64] = a1.w;
        Bs[lc + 0][lr] = b0.x; Bs[lc + 1][lr] = b0.y; Bs[lc + 2][lr] = b0.z; Bs[lc + 3][lr] = b0.w;
        Bs[lc + 0][lr + 64] = b1.x; Bs[lc + 1][lr + 64] = b1.y; Bs[lc + 2][lr + 64] = b1.z; Bs[lc + 3][lr + 64] = b1.w;
        __syncthreads();
        if (k0 < 768) {   // prefetch next K-slab into registers
            a0 = *(const float4*)(Ap + k0);
            a1 = *(const float4*)(Ap + k0 + 64 * 768);
            b0 = *(const float4*)(Bp + k0);
            b1 = *(const float4*)(Bp + k0 + 64 * 768);
        }
#pragma unroll
        for (int kk = 0; kk < 16; kk++) {
            float ar[8], br[8];
            float4 t0 = *(const float4*)&As[kk][ty * 4];
            float4 t1 = *(const float4*)&As[kk][64 + ty * 4];
            float4 u0 = *(const float4*)&Bs[kk][tx * 4];
            float4 u1 = *(const float4*)&Bs[kk][64 + tx * 4];
            ar[0] = t0.x; ar[1] = t0.y; ar[2] = t0.z; ar[3] = t0.w;
            ar[4] = t1.x; ar[5] = t1.y; ar[6] = t1.z; ar[7] = t1.w;
            br[0] = u0.x; br[1] = u0.y; br[2] = u0.z; br[3] = u0.w;
            br[4] = u1.x; br[5] = u1.y; br[6] = u1.z; br[7] = u1.w;
#pragma unroll
            for (int i = 0; i < 8; i++)
#pragma unroll
                for (int j = 0; j < 8; j++)
                    acc[i][j] = fmaf(ar[i], br[j], acc[i][j]);
        }
        __syncthreads();
    }

    const float lam = blend ? *lamb_p : 0.f;
#pragma unroll
    for (int i = 0; i < 8; i++) {
        int r = bm + ((i < 4) ? (ty * 4 + i) : (64 + ty * 4 + (i - 4)));
#pragma unroll
        for (int jg = 0; jg < 2; jg++) {
            int c = bn + jg * 64 + tx * 4;
            float4 v;
            v.x = acc[i][jg * 4 + 0]; v.y = acc[i][jg * 4 + 1];
            v.z = acc[i][jg * 4 + 2]; v.w = acc[i][jg * 4 + 3];
            if (blend) {
                float4 w = *(const float4*)(vi + r * 768 + c);
                v.x = (1.f - lam) * v.x + lam * w.x;
                v.y = (1.f - lam) * v.y + lam * w.y;
                v.z = (1.f - lam) * v.z + lam * w.z;
                v.w = (1.f - lam) * v.w + lam * w.w;
            }
            *(float4*)(C + r * 768 + c) = v;
        }
    }
}

__global__ __launch_bounds__(256) void qkv_gemm_kernel(
    const float* __restrict__ x,
    const float* __restrict__ Wq, const float* __restrict__ Wk, const float* __restrict__ Wv,
    const float* __restrict__ vi, const float* __restrict__ lamb_p)
{
    __shared__ float As[16][132];
    __shared__ float Bs[16][132];
    const int z = blockIdx.z;
    const float* B = (z == 0) ? Wq : (z == 1) ? Wk : Wv;
    float* C = (z == 0) ? g_q : (z == 1) ? g_k : g_v;
    gemm_body(x, B, C, vi, lamb_p, z == 2, As, Bs);
}

__global__ __launch_bounds__(256) void proj_gemm_kernel(
    const float* __restrict__ Wp, float* __restrict__ out)
{
    __shared__ float As[16][132];
    __shared__ float Bs[16][132];
    gemm_body(g_y, Wp, out, nullptr, nullptr, false, As, Bs);
}

// ---------------------------------------------------------------------------
// Per-(t,head) RMS-norm + RoPE for q and k, in place.
// grid (T, NH), 64 threads.
// ---------------------------------------------------------------------------
__global__ void norm_rope_kernel()
{
    const int t = blockIdx.x, h = blockIdx.y;
    const int i = threadIdx.x;
    __shared__ float buf[64];
    __shared__ float wsum[2];
    const int base = t * 768 + h * 64;

#pragma unroll
    for (int which = 0; which < 2; which++) {
        float* ptr = which ? g_k : g_q;
        float v = ptr[base + i];
        float sq = v * v;
#pragma unroll
        for (int off = 16; off; off >>= 1)
            sq += __shfl_xor_sync(0xffffffffu, sq, off);
        if ((i & 31) == 0) wsum[i >> 5] = sq;
        __syncthreads();
        float ms = (wsum[0] + wsum[1]) * (1.f / 64.f);
        float r = rsqrtf(ms + 1.1920928955078125e-7f);  // fp32 machine eps
        buf[i] = v * r;
        __syncthreads();
        if (i < 32) {
            float x1 = buf[i], x2 = buf[i + 32];
            // inv_freq = (1e-4)^(i/32) = 2^(i * log2(1e-4)/32)
            float invf = exp2f((float)i * -0.41524101186092029f);
            float fr = (float)t * invf;
            float s, c;
            sincosf(fr, &s, &c);
            ptr[base + i]      = x1 * c + x2 * s;
            ptr[base + i + 32] = x2 * c - x1 * s;
        }
        __syncthreads();
    }
}

// ---------------------------------------------------------------------------
// Flash-style causal attention, fp32. BM=BN=64, D=64, 256 threads, 4x4 micro.
// Online softmax; K smem tile reused as P buffer. grid (32 qblocks, 12 heads).
// ---------------------------------------------------------------------------
__global__ __launch_bounds__(256) void attn_kernel()
{
    extern __shared__ float sm[];
    float (*Qs)[68]  = (float(*)[68])sm;                 // [d][m]
    float (*KPs)[68] = (float(*)[68])(sm + 64 * 68);     // K phase: [d][n]; P phase: [n][m]
    float (*Vs)[64]  = (float(*)[64])(sm + 2 * 64 * 68); // [n][d]

    const int tid = threadIdx.x;
    const int ty = tid >> 4;   // 0..15 -> rows 4ty..4ty+3
    const int tx = tid & 15;   // 0..15 -> cols 4tx..4tx+3
    const int h  = blockIdx.y;
    const int qb = (int)gridDim.x - 1 - (int)blockIdx.x;  // heavy blocks first

    // load Q tile transposed: Qs[d][m]
#pragma unroll
    for (int it = 0; it < 4; it++) {
        int idx = it * 256 + tid;           // 1024 float4s
        int m = idx >> 4;
        int dg = (idx & 15) << 2;
        float4 v = *(const float4*)(g_q + (qb * 64 + m) * 768 + h * 64 + dg);
        Qs[dg + 0][m] = v.x; Qs[dg + 1][m] = v.y; Qs[dg + 2][m] = v.z; Qs[dg + 3][m] = v.w;
    }

    float o[4][4];
    float mrow[4], lrow[4];
#pragma unroll
    for (int i = 0; i < 4; i++) {
        mrow[i] = -1e30f; lrow[i] = 0.f;
#pragma unroll
        for (int j = 0; j < 4; j++) o[i][j] = 0.f;
    }

    const int nkb = qb + 1;
    for (int kb = 0; kb < nkb; kb++) {
        __syncthreads();   // previous PV done with KPs/Vs
#pragma unroll
        for (int it = 0; it < 4; it++) {
            int idx = it * 256 + tid;
            int n = idx >> 4;
            int dg = (idx & 15) << 2;
            float4 kv = *(const float4*)(g_k + (kb * 64 + n) * 768 + h * 64 + dg);
            KPs[dg + 0][n] = kv.x; KPs[dg + 1][n] = kv.y; KPs[dg + 2][n] = kv.z; KPs[dg + 3][n] = kv.w;
            float4 vv = *(const float4*)(g_v + (kb * 64 + n) * 768 + h * 64 + dg);
            *(float4*)&Vs[n][dg] = vv;
        }
        __syncthreads();

        // S = Q K^T  (4x4 per thread)
        float s[4][4];
#pragma unroll
        for (int i = 0; i < 4; i++)
#pragma unroll
            for (int j = 0; j < 4; j++) s[i][j] = 0.f;

#pragma unroll 16
        for (int d = 0; d < 64; d++) {
            float4 aq = *(const float4*)&Qs[d][ty * 4];
            float4 bk = *(const float4*)&KPs[d][tx * 4];
            float a[4] = {aq.x, aq.y, aq.z, aq.w};
            float b[4] = {bk.x, bk.y, bk.z, bk.w};
#pragma unroll
            for (int i = 0; i < 4; i++)
#pragma unroll
                for (int j = 0; j < 4; j++)
                    s[i][j] = fmaf(a[i], b[j], s[i][j]);
        }

#pragma unroll
        for (int i = 0; i < 4; i++)
#pragma unroll
            for (int j = 0; j < 4; j++) s[i][j] *= 0.125f;   // 1/sqrt(64)

        if (kb == qb) {   // diagonal block: causal mask
#pragma unroll
            for (int i = 0; i < 4; i++)
#pragma unroll
                for (int j = 0; j < 4; j++)
                    if (tx * 4 + j > ty * 4 + i) s[i][j] = -1e30f;
        }

        // online softmax (rows 4ty+i owned by the 16 tx-threads of this ty)
        float p[4][4];
#pragma unroll
        for (int i = 0; i < 4; i++) {
            float rmax = s[i][0];
#pragma unroll
            for (int j = 1; j < 4; j++) rmax = fmaxf(rmax, s[i][j]);
#pragma unroll
            for (int off = 8; off; off >>= 1)
                rmax = fmaxf(rmax, __shfl_xor_sync(0xffffffffu, rmax, off, 16));
            float mnew = fmaxf(mrow[i], rmax);
            float corr = __expf(mrow[i] - mnew);
            float psum = 0.f;
#pragma unroll
            for (int j = 0; j < 4; j++) {
                p[i][j] = __expf(s[i][j] - mnew);
                psum += p[i][j];
            }
#pragma unroll
            for (int off = 8; off; off >>= 1)
                psum += __shfl_xor_sync(0xffffffffu, psum, off, 16);
            lrow[i] = lrow[i] * corr + psum;
            mrow[i] = mnew;
#pragma unroll
            for (int j = 0; j < 4; j++) o[i][j] *= corr;
        }

        __syncthreads();   // everyone done reading K from KPs
        // write P transposed: KPs[n][m]
#pragma unroll
        for (int j = 0; j < 4; j++)
#pragma unroll
            for (int i = 0; i < 4; i++)
                KPs[tx * 4 + j][ty * 4 + i] = p[i][j];
        __syncthreads();

        // O += P V
#pragma unroll 16
        for (int n = 0; n < 64; n++) {
            float4 pp = *(const float4*)&KPs[n][ty * 4];
            float4 vv = *(const float4*)&Vs[n][tx * 4];
            float a[4] = {pp.x, pp.y, pp.z, pp.w};
            float b[4] = {vv.x, vv.y, vv.z, vv.w};
#pragma unroll
            for (int i = 0; i < 4; i++)
#pragma unroll
                for (int j = 0; j < 4; j++)
                    o[i][j] = fmaf(a[i], b[j], o[i][j]);
        }
    }

    // normalize + store y[t, h*64 + d]
#pragma unroll
    for (int i = 0; i < 4; i++) {
        float inv = 1.f / lrow[i];
        float4 v;
        v.x = o[i][0] * inv; v.y = o[i][1] * inv;
        v.z = o[i][2] * inv; v.w = o[i][3] * inv;
        *(float4*)(g_y + (qb * 64 + ty * 4 + i) * 768 + h * 64 + tx * 4) = v;
    }
}

// ---------------------------------------------------------------------------
extern "C" void kernel_launch(void* const* d_in, const int* in_sizes, int n_in,
                              void* d_out, int out_size)
{
    (void)in_sizes; (void)n_in; (void)out_size;
    const float* x    = (const float*)d_in[0];
    const float* vi   = (const float*)d_in[1];
    const float* Wq   = (const float*)d_in[2];
    const float* Wk   = (const float*)d_in[3];
    const float* Wv   = (const float*)d_in[4];
    const float* Wp   = (const float*)d_in[5];
    const float* lamb = (const float*)d_in[6];
    float* out = (float*)d_out;

    qkv_gemm_kernel<<<dim3(6, 16, 3), 256>>>(x, Wq, Wk, Wv, vi, lamb);
    norm_rope_kernel<<<dim3(TT, NH), 64>>>();

    const size_t attn_smem = (size_t)(2 * 64 * 68 + 64 * 64) * sizeof(float); // 51200 B
    cudaFuncSetAttribute(attn_kernel, cudaFuncAttributeMaxDynamicSharedMemorySize,
                         (int)attn_smem);
    attn_kernel<<<dim3(32, NH), 256, attn_smem>>>();

    proj_gemm_kernel<<<dim3(6, 16), 256>>>(Wp, out);
}

// round 12
// speedup vs baseline: 1.3847x; 1.3847x over previous
#include <cuda_runtime.h>
#include <mma.h>
#include <math.h>
#include <stdint.h>

using namespace nvcuda;

#define TT 2048
#define NH 12

// scratch (device globals: no allocations allowed)
__device__ float g_q[TT * 768];
__device__ float g_k[TT * 768];
__device__ float g_v[TT * 768];
__device__ float g_y[TT * 768];

typedef wmma::fragment<wmma::matrix_a, 16, 16, 8, wmma::precision::tf32, wmma::row_major> FragA;
typedef wmma::fragment<wmma::matrix_b, 16, 16, 8, wmma::precision::tf32, wmma::col_major> FragBc;
typedef wmma::fragment<wmma::matrix_b, 16, 16, 8, wmma::precision::tf32, wmma::row_major> FragBr;
typedef wmma::fragment<wmma::accumulator, 16, 16, 8, float> FragC;

template <typename F>
__device__ __forceinline__ void to_tf32(F& f) {
#pragma unroll
    for (int i = 0; i < f.num_elements; i++) f.x[i] = wmma::__float_to_tf32(f.x[i]);
}

// ===========================================================================
// tf32 WMMA GEMM:  C[2048,768] = A[2048,768] @ W[768,768]^T
// Block tile 128(M) x 64(N), K-chunk 16, double-buffered smem, 256 threads.
// Warp grid 4(M) x 2(N); each warp 32x32 = 2x2 fragments of 16x16.
// ===========================================================================
#define GK 16
#define NCHUNK 48           // 768 / 16
#define ALD 20              // smem leading dim (floats), mult of 4

__device__ __forceinline__ void gemm_tf32_body(
    const float* __restrict__ A, const float* __restrict__ W,
    float* __restrict__ C, const float* __restrict__ vi,
    const float* __restrict__ lamb_p, bool blend,
    float (*As)[ALD], float (*Bs)[ALD])   // As: [2*128][ALD], Bs: [2*64][ALD]
{
    const int tid = threadIdx.x;
    const int wid = tid >> 5;
    const int wm = wid & 3;        // 0..3  -> rows wm*32
    const int wn = wid >> 2;       // 0..1  -> cols wn*32
    const int bm = blockIdx.y * 128;
    const int bn = blockIdx.x * 64;

    FragC acc[2][2];
#pragma unroll
    for (int i = 0; i < 2; i++)
#pragma unroll
        for (int j = 0; j < 2; j++) wmma::fill_fragment(acc[i][j], 0.f);

    // tile loader: A 128x16 (512 float4, 2/thread), W 64x16 (256 float4, 1/thread)
    auto load_tile = [&](int c, int buf) {
        const int k0 = c * GK;
#pragma unroll
        for (int it = 0; it < 2; it++) {
            int idx = it * 256 + tid;
            int r = idx >> 2, c4 = idx & 3;
            float4 v = *(const float4*)(A + (size_t)(bm + r) * 768 + k0 + c4 * 4);
            *(float4*)&As[buf * 128 + r][c4 * 4] = v;
        }
        {
            int r = tid >> 2, c4 = tid & 3;
            float4 v = *(const float4*)(W + (size_t)(bn + r) * 768 + k0 + c4 * 4);
            *(float4*)&Bs[buf * 64 + r][c4 * 4] = v;
        }
    };

    load_tile(0, 0);
    __syncthreads();

    for (int c = 0; c < NCHUNK; c++) {
        const int buf = c & 1;
#pragma unroll
        for (int ks = 0; ks < 2; ks++) {
            FragA a[2];
            FragBc b[2];
#pragma unroll
            for (int i = 0; i < 2; i++) {
                wmma::load_matrix_sync(a[i], &As[buf * 128 + wm * 32 + i * 16][ks * 8], ALD);
                to_tf32(a[i]);
            }
#pragma unroll
            for (int j = 0; j < 2; j++) {
                wmma::load_matrix_sync(b[j], &Bs[buf * 64 + wn * 32 + j * 16][ks * 8], ALD);
                to_tf32(b[j]);
            }
#pragma unroll
            for (int i = 0; i < 2; i++)
#pragma unroll
                for (int j = 0; j < 2; j++)
                    wmma::mma_sync(acc[i][j], a[i], b[j], acc[i][j]);
        }
        if (c + 1 < NCHUNK) load_tile(c + 1, buf ^ 1);
        __syncthreads();
    }

    const float lam = blend ? *lamb_p : 0.f;
#pragma unroll
    for (int i = 0; i < 2; i++)
#pragma unroll
        for (int j = 0; j < 2; j++) {
            const int r0 = bm + wm * 32 + i * 16;
            const int c0 = bn + wn * 32 + j * 16;
            if (blend) {
                FragC vf;
                wmma::load_matrix_sync(vf, vi + (size_t)r0 * 768 + c0, 768, wmma::mem_row_major);
#pragma unroll
                for (int t = 0; t < acc[i][j].num_elements; t++)
                    acc[i][j].x[t] = (1.f - lam) * acc[i][j].x[t] + lam * vf.x[t];
            }
            wmma::store_matrix_sync(C + (size_t)r0 * 768 + c0, acc[i][j], 768, wmma::mem_row_major);
        }
}

__global__ __launch_bounds__(256) void qkv_gemm_kernel(
    const float* __restrict__ x,
    const float* __restrict__ Wq, const float* __restrict__ Wk, const float* __restrict__ Wv,
    const float* __restrict__ vi, const float* __restrict__ lamb_p)
{
    __shared__ float As[2 * 128][ALD];
    __shared__ float Bs[2 * 64][ALD];
    const int z = blockIdx.z;
    const float* B = (z == 0) ? Wq : (z == 1) ? Wk : Wv;
    float* C = (z == 0) ? g_q : (z == 1) ? g_k : g_v;
    gemm_tf32_body(x, B, C, vi, lamb_p, z == 2, As, Bs);
}

__global__ __launch_bounds__(256) void proj_gemm_kernel(
    const float* __restrict__ Wp, float* __restrict__ out)
{
    __shared__ float As[2 * 128][ALD];
    __shared__ float Bs[2 * 64][ALD];
    gemm_tf32_body(g_y, Wp, out, nullptr, nullptr, false, As, Bs);
}

// ---------------------------------------------------------------------------
// Per-(t,head) RMS-norm + RoPE for q and k, in place. grid (T, NH), 64 thr.
// ---------------------------------------------------------------------------
__global__ void norm_rope_kernel()
{
    const int t = blockIdx.x, h = blockIdx.y;
    const int i = threadIdx.x;
    __shared__ float buf[64];
    __shared__ float wsum[2];
    const int base = t * 768 + h * 64;

#pragma unroll
    for (int which = 0; which < 2; which++) {
        float* ptr = which ? g_k : g_q;
        float v = ptr[base + i];
        float sq = v * v;
#pragma unroll
        for (int off = 16; off; off >>= 1)
            sq += __shfl_xor_sync(0xffffffffu, sq, off);
        if ((i & 31) == 0) wsum[i >> 5] = sq;
        __syncthreads();
        float ms = (wsum[0] + wsum[1]) * (1.f / 64.f);
        float r = rsqrtf(ms + 1.1920928955078125e-7f);  // fp32 machine eps
        buf[i] = v * r;
        __syncthreads();
        if (i < 32) {
            float x1 = buf[i], x2 = buf[i + 32];
            float invf = exp2f((float)i * -0.41524101186092029f);
            float fr = (float)t * invf;
            float s, c;
            sincosf(fr, &s, &c);
            ptr[base + i]      = x1 * c + x2 * s;
            ptr[base + i + 32] = x2 * c - x1 * s;
        }
        __syncthreads();
    }
}

// ===========================================================================
// Flash-style causal attention with WMMA tf32 for QK^T and PV.
// BM=BN=64, D=64, 256 threads = 8 warps (4 m x 2 n, 16x32 per warp).
// Online softmax + O accumulation in SIMT registers (row-mapped), P*V result
// round-trips through smem (reusing the K tile region).
// grid (32 qblocks, 12 heads).
// ===========================================================================
#define SLD 68    // smem leading dim for 64-wide tiles

__global__ __launch_bounds__(256) void attn_kernel()
{
    extern __shared__ float sm[];
    float* Qs = sm;                 // [64][SLD] row=m, col=d
    float* Ks = sm + 64 * SLD;      // [64][SLD] row=n, col=d  (reused for PV result)
    float* Vs = sm + 2 * 64 * SLD;  // [64][SLD] row=n, col=d
    float* Ss = sm + 3 * 64 * SLD;  // [64][SLD] row=m, col=n  (S, then P)

    const int tid = threadIdx.x;
    const int wid = tid >> 5;
    const int wm = wid & 3;         // S rows wm*16
    const int wn = wid >> 2;        // S cols wn*32
    const int h  = blockIdx.y;
    const int qb = (int)gridDim.x - 1 - (int)blockIdx.x;   // heavy blocks first

    // softmax ownership: row = tid>>2 (0..63), quad thread t = tid&3 -> cols t*16..t*16+15
    const int srow = tid >> 2;
    const int squad = tid & 3;

    // load Q tile
#pragma unroll
    for (int it = 0; it < 4; it++) {
        int idx = it * 256 + tid;
        int m = idx >> 4;
        int dg = (idx & 15) << 2;
        float4 v = *(const float4*)(g_q + (size_t)(qb * 64 + m) * 768 + h * 64 + dg);
        *(float4*)&Qs[m * SLD + dg] = v;
    }

    float O[16];
#pragma unroll
    for (int j = 0; j < 16; j++) O[j] = 0.f;
    float mrow = -1e30f, lrow = 0.f;

    const int nkb = qb + 1;
    for (int kb = 0; kb < nkb; kb++) {
        __syncthreads();   // prev iter's O-update done; K/V/S areas free
#pragma unroll
        for (int it = 0; it < 4; it++) {
            int idx = it * 256 + tid;
            int n = idx >> 4;
            int dg = (idx & 15) << 2;
            float4 kv = *(const float4*)(g_k + (size_t)(kb * 64 + n) * 768 + h * 64 + dg);
            *(float4*)&Ks[n * SLD + dg] = kv;
            float4 vv = *(const float4*)(g_v + (size_t)(kb * 64 + n) * 768 + h * 64 + dg);
            *(float4*)&Vs[n * SLD + dg] = vv;
        }
        __syncthreads();

        // ---- S = Q K^T (warp-level wmma) ----
        {
            FragC sacc[2];
            wmma::fill_fragment(sacc[0], 0.f);
            wmma::fill_fragment(sacc[1], 0.f);
#pragma unroll
            for (int ks = 0; ks < 8; ks++) {
                FragA a;
                wmma::load_matrix_sync(a, &Qs[wm * 16 * SLD + ks * 8], SLD);
                to_tf32(a);
#pragma unroll
                for (int j = 0; j < 2; j++) {
                    FragBc b;
                    wmma::load_matrix_sync(b, &Ks[(wn * 32 + j * 16) * SLD + ks * 8], SLD);
                    to_tf32(b);
                    wmma::mma_sync(sacc[j], a, b, sacc[j]);
                }
            }
#pragma unroll
            for (int j = 0; j < 2; j++)
                wmma::store_matrix_sync(&Ss[wm * 16 * SLD + wn * 32 + j * 16], sacc[j],
                                        SLD, wmma::mem_row_major);
        }
        __syncthreads();

        // ---- online softmax (SIMT, row-mapped) ----
        {
            const bool diag = (kb == qb);
            float s[16];
            float rmax = -1e30f;
#pragma unroll
            for (int j = 0; j < 16; j++) {
                int c = squad * 16 + j;
                float v = Ss[srow * SLD + c] * 0.125f;
                if (diag && c > srow) v = -1e30f;
                s[j] = v;
                rmax = fmaxf(rmax, v);
            }
            rmax = fmaxf(rmax, __shfl_xor_sync(0xffffffffu, rmax, 1));
            rmax = fmaxf(rmax, __shfl_xor_sync(0xffffffffu, rmax, 2));
            float mnew = fmaxf(mrow, rmax);
            float corr = __expf(mrow - mnew);
            float psum = 0.f;
#pragma unroll
            for (int j = 0; j < 16; j++) {
                float p = __expf(s[j] - mnew);
                psum += p;
                Ss[srow * SLD + squad * 16 + j] = p;
            }
            psum += __shfl_xor_sync(0xffffffffu, psum, 1);
            psum += __shfl_xor_sync(0xffffffffu, psum, 2);
            lrow = lrow * corr + psum;
            mrow = mnew;
#pragma unroll
            for (int j = 0; j < 16; j++) O[j] *= corr;
        }
        __syncthreads();

        // ---- PV = P @ V (wmma), result into Ks region ----
        {
            FragC pacc[2];
            wmma::fill_fragment(pacc[0], 0.f);
            wmma::fill_fragment(pacc[1], 0.f);
#pragma unroll
            for (int ks = 0; ks < 8; ks++) {
                FragA a;
                wmma::load_matrix_sync(a, &Ss[wm * 16 * SLD + ks * 8], SLD);
                to_tf32(a);
#pragma unroll
                for (int j = 0; j < 2; j++) {
                    FragBr b;
                    wmma::load_matrix_sync(b, &Vs[ks * 8 * SLD + wn * 32 + j * 16], SLD);
                    to_tf32(b);
                    wmma::mma_sync(pacc[j], a, b, pacc[j]);
                }
            }
#pragma unroll
            for (int j = 0; j < 2; j++)
                wmma::store_matrix_sync(&Ks[wm * 16 * SLD + wn * 32 + j * 16], pacc[j],
                                        SLD, wmma::mem_row_major);
        }
        __syncthreads();

        // ---- O += PV (SIMT, row-mapped) ----
#pragma unroll
        for (int j = 0; j < 16; j++)
            O[j] += Ks[srow * SLD + squad * 16 + j];
    }

    // normalize + store y
    {
        float inv = 1.f / lrow;
        float* yp = g_y + (size_t)(qb * 64 + srow) * 768 + h * 64 + squad * 16;
#pragma unroll
        for (int j = 0; j < 16; j += 4) {
            float4 v;
            v.x = O[j + 0] * inv; v.y = O[j + 1] * inv;
            v.z = O[j + 2] * inv; v.w = O[j + 3] * inv;
            *(float4*)(yp + j) = v;
        }
    }
}

// ---------------------------------------------------------------------------
extern "C" void kernel_launch(void* const* d_in, const int* in_sizes, int n_in,
                              void* d_out, int out_size)
{
    (void)in_sizes; (void)n_in; (void)out_size;
    const float* x    = (const float*)d_in[0];
    const float* vi   = (const float*)d_in[1];
    const float* Wq   = (const float*)d_in[2];
    const float* Wk   = (const float*)d_in[3];
    const float* Wv   = (const float*)d_in[4];
    const float* Wp   = (const float*)d_in[5];
    const float* lamb = (const float*)d_in[6];
    float* out = (float*)d_out;

    qkv_gemm_kernel<<<dim3(12, 16, 3), 256>>>(x, Wq, Wk, Wv, vi, lamb);
    norm_rope_kernel<<<dim3(TT, NH), 64>>>();

    const int attn_smem = 4 * 64 * SLD * sizeof(float);   // 69632 B
    cudaFuncSetAttribute(attn_kernel, cudaFuncAttributeMaxDynamicSharedMemorySize, attn_smem);
    attn_kernel<<<dim3(32, NH), 256, attn_smem>>>();

    proj_gemm_kernel<<<dim3(12, 16), 256>>>(Wp, out);
}

// round 16
// speedup vs baseline: 1.4974x; 1.0814x over previous
#include <cuda_runtime.h>
#include <mma.h>
#include <math.h>
#include <stdint.h>

using namespace nvcuda;

#define TT 2048
#define NH 12

// scratch (device globals: no allocations allowed)
__device__ float g_q[TT * 768];
__device__ float g_k[TT * 768];
__device__ float g_v[TT * 768];
__device__ float g_y[TT * 768];

typedef wmma::fragment<wmma::matrix_a, 16, 16, 8, wmma::precision::tf32, wmma::row_major> FragA;
typedef wmma::fragment<wmma::matrix_b, 16, 16, 8, wmma::precision::tf32, wmma::col_major> FragBc;
typedef wmma::fragment<wmma::matrix_b, 16, 16, 8, wmma::precision::tf32, wmma::row_major> FragBr;
typedef wmma::fragment<wmma::accumulator, 16, 16, 8, float> FragC;

__device__ __forceinline__ float rtf32(float x) { return wmma::__float_to_tf32(x); }
__device__ __forceinline__ float4 rtf32_4(float4 v) {
    v.x = rtf32(v.x); v.y = rtf32(v.y); v.z = rtf32(v.z); v.w = rtf32(v.w);
    return v;
}

// ===========================================================================
// tf32 WMMA GEMM:  C[2048,768] = A[2048,768] @ W[768,768]^T
// BM=128, BN=64, BK=16, 128 threads = 4 warps (2m x 2n), warp tile 64x32.
// Inputs pre-rounded to tf32 in the smem loader (no per-fragment F2F).
// ===========================================================================
#define GBM 128
#define GBN 64
#define GBK 16
#define GALD 20
#define GCHUNK 48

__device__ __forceinline__ void gemm_tf32_body(
    const float* __restrict__ A, const float* __restrict__ W,
    float* __restrict__ C, const float* __restrict__ vi,
    const float* __restrict__ lamb_p, bool blend,
    float (*As)[GALD], float (*Bs)[GALD])  // As:[2*128][GALD] Bs:[2*64][GALD]
{
    const int tid = threadIdx.x;
    const int wid = tid >> 5;
    const int wm = wid & 1;        // 0..1 -> rows wm*64
    const int wn = wid >> 1;       // 0..1 -> cols wn*32
    const int bm = blockIdx.y * GBM;
    const int bn = blockIdx.x * GBN;

    FragC acc[4][2];
#pragma unroll
    for (int i = 0; i < 4; i++)
#pragma unroll
        for (int j = 0; j < 2; j++) wmma::fill_fragment(acc[i][j], 0.f);

    auto load_tile = [&](int c, int buf) {
        const int k0 = c * GBK;
#pragma unroll
        for (int it = 0; it < 4; it++) {   // A: 512 float4, 4/thread
            int idx = it * 128 + tid;
            int r = idx >> 2, c4 = idx & 3;
            float4 v = *(const float4*)(A + (size_t)(bm + r) * 768 + k0 + c4 * 4);
            *(float4*)&As[buf * 128 + r][c4 * 4] = rtf32_4(v);
        }
#pragma unroll
        for (int it = 0; it < 2; it++) {   // B: 256 float4, 2/thread
            int idx = it * 128 + tid;
            int r = idx >> 2, c4 = idx & 3;
            float4 v = *(const float4*)(W + (size_t)(bn + r) * 768 + k0 + c4 * 4);
            *(float4*)&Bs[buf * 64 + r][c4 * 4] = rtf32_4(v);
        }
    };

    load_tile(0, 0);
    __syncthreads();

    for (int c = 0; c < GCHUNK; c++) {
        const int buf = c & 1;
#pragma unroll
        for (int ks = 0; ks < 2; ks++) {
            FragA a[4];
            FragBc b[2];
#pragma unroll
            for (int i = 0; i < 4; i++)
                wmma::load_matrix_sync(a[i], &As[buf * 128 + wm * 64 + i * 16][ks * 8], GALD);
#pragma unroll
            for (int j = 0; j < 2; j++)
                wmma::load_matrix_sync(b[j], &Bs[buf * 64 + wn * 32 + j * 16][ks * 8], GALD);
#pragma unroll
            for (int i = 0; i < 4; i++)
#pragma unroll
                for (int j = 0; j < 2; j++)
                    wmma::mma_sync(acc[i][j], a[i], b[j], acc[i][j]);
        }
        if (c + 1 < GCHUNK) load_tile(c + 1, buf ^ 1);
        __syncthreads();
    }

    const float lam = blend ? *lamb_p : 0.f;
#pragma unroll
    for (int i = 0; i < 4; i++)
#pragma unroll
        for (int j = 0; j < 2; j++) {
            const int r0 = bm + wm * 64 + i * 16;
            const int c0 = bn + wn * 32 + j * 16;
            if (blend) {
                FragC vf;
                wmma::load_matrix_sync(vf, vi + (size_t)r0 * 768 + c0, 768, wmma::mem_row_major);
#pragma unroll
                for (int t = 0; t < acc[i][j].num_elements; t++)
                    acc[i][j].x[t] = (1.f - lam) * acc[i][j].x[t] + lam * vf.x[t];
            }
            wmma::store_matrix_sync(C + (size_t)r0 * 768 + c0, acc[i][j], 768, wmma::mem_row_major);
        }
}

__global__ __launch_bounds__(128) void qkv_gemm_kernel(
    const float* __restrict__ x,
    const float* __restrict__ Wq, const float* __restrict__ Wk, const float* __restrict__ Wv,
    const float* __restrict__ vi, const float* __restrict__ lamb_p)
{
    __shared__ float As[2 * 128][GALD];
    __shared__ float Bs[2 * 64][GALD];
    const int z = blockIdx.z;
    const float* B = (z == 0) ? Wq : (z == 1) ? Wk : Wv;
    float* C = (z == 0) ? g_q : (z == 1) ? g_k : g_v;
    gemm_tf32_body(x, B, C, vi, lamb_p, z == 2, As, Bs);
}

__global__ __launch_bounds__(128) void proj_gemm_kernel(
    const float* __restrict__ Wp, float* __restrict__ out)
{
    __shared__ float As[2 * 128][GALD];
    __shared__ float Bs[2 * 64][GALD];
    gemm_tf32_body(g_y, Wp, out, nullptr, nullptr, false, As, Bs);
}

// ---------------------------------------------------------------------------
// Per-(t,head) RMS-norm + RoPE for q and k, in place. grid (T, NH), 64 thr.
// ---------------------------------------------------------------------------
__global__ void norm_rope_kernel()
{
    const int t = blockIdx.x, h = blockIdx.y;
    const int i = threadIdx.x;
    __shared__ float buf[64];
    __shared__ float wsum[2];
    const int base = t * 768 + h * 64;

#pragma unroll
    for (int which = 0; which < 2; which++) {
        float* ptr = which ? g_k : g_q;
        float v = ptr[base + i];
        float sq = v * v;
#pragma unroll
        for (int off = 16; off; off >>= 1)
            sq += __shfl_xor_sync(0xffffffffu, sq, off);
        if ((i & 31) == 0) wsum[i >> 5] = sq;
        __syncthreads();
        float ms = (wsum[0] + wsum[1]) * (1.f / 64.f);
        float r = rsqrtf(ms + 1.1920928955078125e-7f);  // fp32 machine eps
        buf[i] = v * r;
        __syncthreads();
        if (i < 32) {
            float x1 = buf[i], x2 = buf[i + 32];
            float invf = exp2f((float)i * -0.41524101186092029f);
            float fr = (float)t * invf;
            float s, c;
            sincosf(fr, &s, &c);
            ptr[base + i]      = x1 * c + x2 * s;
            ptr[base + i + 32] = x2 * c - x1 * s;
        }
        __syncthreads();
    }
}

// ===========================================================================
// Flash-style causal attention, WMMA tf32, static-max softmax.
// q,k RMS-normalized => |s| <= 8, so p = exp(s - 8) needs no online rescale:
// O accumulates in persistent WMMA accumulators; l accumulates per thread.
// BM=BN=64, D=64, 256 threads = 8 warps (4m x 2n). grid (32 qblocks, 12 heads).
// ===========================================================================
#define SLD 68

__global__ __launch_bounds__(256) void attn_kernel()
{
    extern __shared__ float sm[];
    float* Qs = sm;                 // [64][SLD]  (pre-scaled by 0.125, tf32)
    float* Ks = sm + 64 * SLD;      // [64][SLD]
    float* Vs = sm + 2 * 64 * SLD;  // [64][SLD]
    float* Ss = sm + 3 * 64 * SLD;  // [64][SLD]  S -> P -> final O

    const int tid = threadIdx.x;
    const int wid = tid >> 5;
    const int wm = wid & 3;         // rows wm*16
    const int wn = wid >> 2;        // cols wn*32
    const int h  = blockIdx.y;
    const int qb = (int)gridDim.x - 1 - (int)blockIdx.x;   // heavy blocks first

    const int srow = tid >> 2;      // 0..63
    const int squad = tid & 3;      // cols squad*16..+15

    // load Q tile (scale folded, tf32-rounded)
#pragma unroll
    for (int it = 0; it < 4; it++) {
        int idx = it * 256 + tid;
        int m = idx >> 4;
        int dg = (idx & 15) << 2;
        float4 v = *(const float4*)(g_q + (size_t)(qb * 64 + m) * 768 + h * 64 + dg);
        v.x *= 0.125f; v.y *= 0.125f; v.z *= 0.125f; v.w *= 0.125f;
        *(float4*)&Qs[m * SLD + dg] = rtf32_4(v);
    }

    FragC oacc[2];
    wmma::fill_fragment(oacc[0], 0.f);
    wmma::fill_fragment(oacc[1], 0.f);
    float lpart = 0.f;

    const int nkb = qb + 1;
    for (int kb = 0; kb < nkb; kb++) {
        __syncthreads();   // previous PV done reading Ss/Vs; Ks free
#pragma unroll
        for (int it = 0; it < 4; it++) {
            int idx = it * 256 + tid;
            int n = idx >> 4;
            int dg = (idx & 15) << 2;
            float4 kv = *(const float4*)(g_k + (size_t)(kb * 64 + n) * 768 + h * 64 + dg);
            *(float4*)&Ks[n * SLD + dg] = rtf32_4(kv);
            float4 vv = *(const float4*)(g_v + (size_t)(kb * 64 + n) * 768 + h * 64 + dg);
            *(float4*)&Vs[n * SLD + dg] = rtf32_4(vv);
        }
        __syncthreads();

        // ---- S = (Q*scale) K^T ----
        {
            FragC sacc[2];
            wmma::fill_fragment(sacc[0], 0.f);
            wmma::fill_fragment(sacc[1], 0.f);
#pragma unroll
            for (int ks = 0; ks < 8; ks++) {
                FragA a;
                wmma::load_matrix_sync(a, &Qs[wm * 16 * SLD + ks * 8], SLD);
#pragma unroll
                for (int j = 0; j < 2; j++) {
                    FragBc b;
                    wmma::load_matrix_sync(b, &Ks[(wn * 32 + j * 16) * SLD + ks * 8], SLD);
                    wmma::mma_sync(sacc[j], a, b, sacc[j]);
                }
            }
#pragma unroll
            for (int j = 0; j < 2; j++)
                wmma::store_matrix_sync(&Ss[wm * 16 * SLD + wn * 32 + j * 16], sacc[j],
                                        SLD, wmma::mem_row_major);
        }
        __syncthreads();

        // ---- p = exp(s - 8), masked; accumulate l; write P (tf32) ----
        {
            const bool diag = (kb == qb);
            float psum = 0.f;
#pragma unroll
            for (int j = 0; j < 16; j++) {
                int c = squad * 16 + j;
                float p;
                if (diag && c > srow) {
                    p = 0.f;
                } else {
                    p = __expf(Ss[srow * SLD + c] - 8.f);
                }
                psum += p;
                Ss[srow * SLD + c] = rtf32(p);
            }
            lpart += psum;
        }
        __syncthreads();

        // ---- O += P V (persistent accumulators) ----
#pragma unroll
        for (int ks = 0; ks < 8; ks++) {
            FragA a;
            wmma::load_matrix_sync(a, &Ss[wm * 16 * SLD + ks * 8], SLD);
#pragma unroll
            for (int j = 0; j < 2; j++) {
                FragBr b;
                wmma::load_matrix_sync(b, &Vs[(ks * 8) * SLD + wn * 32 + j * 16], SLD);
                wmma::mma_sync(oacc[j], a, b, oacc[j]);
            }
        }
    }

    // park O in smem, then normalize rows and store
    __syncthreads();
#pragma unroll
    for (int j = 0; j < 2; j++)
        wmma::store_matrix_sync(&Ss[wm * 16 * SLD + wn * 32 + j * 16], oacc[j],
                                SLD, wmma::mem_row_major);
    __syncthreads();

    {
        float l = lpart;
        l += __shfl_xor_sync(0xffffffffu, l, 1);
        l += __shfl_xor_sync(0xffffffffu, l, 2);
        float inv = 1.f / l;
        float* yp = g_y + (size_t)(qb * 64 + srow) * 768 + h * 64 + squad * 16;
#pragma unroll
        for (int j = 0; j < 16; j += 4) {
            float4 v;
            v.x = Ss[srow * SLD + squad * 16 + j + 0] * inv;
            v.y = Ss[srow * SLD + squad * 16 + j + 1] * inv;
            v.z = Ss[srow * SLD + squad * 16 + j + 2] * inv;
            v.w = Ss[srow * SLD + squad * 16 + j + 3] * inv;
            *(float4*)(yp + j) = v;
        }
    }
}

// ---------------------------------------------------------------------------
extern "C" void kernel_launch(void* const* d_in, const int* in_sizes, int n_in,
                              void* d_out, int out_size)
{
    (void)in_sizes; (void)n_in; (void)out_size;
    const float* x    = (const float*)d_in[0];
    const float* vi   = (const float*)d_in[1];
    const float* Wq   = (const float*)d_in[2];
    const float* Wk   = (const float*)d_in[3];
    const float* Wv   = (const float*)d_in[4];
    const float* Wp   = (const float*)d_in[5];
    const float* lamb = (const float*)d_in[6];
    float* out = (float*)d_out;

    qkv_gemm_kernel<<<dim3(12, 16, 3), 128>>>(x, Wq, Wk, Wv, vi, lamb);
    norm_rope_kernel<<<dim3(TT, NH), 64>>>();

    const int attn_smem = 4 * 64 * SLD * sizeof(float);   // 69632 B
    cudaFuncSetAttribute(attn_kernel, cudaFuncAttributeMaxDynamicSharedMemorySize, attn_smem);
    attn_kernel<<<dim3(32, NH), 256, attn_smem>>>();

    proj_gemm_kernel<<<dim3(12, 16), 128>>>(Wp, out);
}